// round 7
// baseline (speedup 1.0000x reference)
#include <cuda_runtime.h>
#include <cuda_bf16.h>
#include <math.h>

#define DDIM  512
#define PCNT  64
#define CCNT  100
#define NBOX  4096
#define G     8            // boxes per tile
#define TILES 32           // covers up to 256 boxes per class (max ~65 expected)

// ---- device scratch (static allocations only) ----
__device__ float g_pT[CCNT * DDIM * PCNT];   // transposed protos: float2 view [C][256][64]
__device__ float g_psq[CCNT * PCNT];         // ||p||^2
__device__ int   g_hist[CCNT];
__device__ int   g_off[CCNT];
__device__ int   g_cur[CCNT];
__device__ int   g_sorted[NBOX];

// ---- prologue 0: zero counters ----
__global__ void zero_kernel() {
    int t = threadIdx.x;
    if (t < CCNT) { g_hist[t] = 0; g_cur[t] = 0; }
}

// ---- prologue 1: class histogram ----
__global__ void hist_kernel(const int* __restrict__ cls_ids) {
    int n = blockIdx.x * 256 + threadIdx.x;
    if (n < NBOX) atomicAdd(&g_hist[cls_ids[n]], 1);
}

// ---- prologue 2: exclusive prefix sum over 100 classes ----
__global__ void scan_kernel() {
    __shared__ int h[CCNT];
    int t = threadIdx.x;
    if (t < CCNT) h[t] = g_hist[t];
    __syncthreads();
    if (t == 0) {
        int run = 0;
        for (int c = 0; c < CCNT; c++) { g_off[c] = run; run += h[c]; }
    }
}

// ---- prologue 3: scatter box ids by class ----
__global__ void scatter_kernel(const int* __restrict__ cls_ids) {
    int n = blockIdx.x * 256 + threadIdx.x;
    if (n < NBOX) {
        int c = cls_ids[n];
        int pos = atomicAdd(&g_cur[c], 1);
        g_sorted[g_off[c] + pos] = n;
    }
}

// ---- prologue 4: transpose protos [C][P][D] -> float2 [C][D/2][P] ----
__global__ void transpose_kernel(const float* __restrict__ protos) {
    __shared__ float tile[32][33];
    const int c  = blockIdx.z;
    const int p0 = blockIdx.y * 32;
    const int d0 = blockIdx.x * 32;
    const int t  = threadIdx.x;
    #pragma unroll
    for (int it = 0; it < 4; it++) {
        int e = t + it * 256;
        int lp = e >> 5, ld = e & 31;
        tile[lp][ld] = protos[((size_t)(c * PCNT + p0 + lp)) * DDIM + d0 + ld];
    }
    __syncthreads();
    #pragma unroll
    for (int it = 0; it < 4; it++) {
        int e = t + it * 256;
        int ld = e >> 5, lp = e & 31;       // now ld indexes d, lp indexes p
        int d = d0 + ld, p = p0 + lp;
        g_pT[(((size_t)c * 256 + (d >> 1)) * PCNT + p) * 2 + (d & 1)] = tile[lp][ld];
    }
}

// ---- prologue 5: ||p||^2 per prototype ----
__global__ __launch_bounds__(256) void psq_kernel(const float* __restrict__ protos) {
    const int row  = blockIdx.x * 8 + (threadIdx.x >> 5);
    const int lane = threadIdx.x & 31;
    if (row >= CCNT * PCNT) return;
    const float4* pv = reinterpret_cast<const float4*>(protos + (size_t)row * DDIM);
    float s = 0.f;
    #pragma unroll
    for (int j = 0; j < 4; j++) {
        float4 a = __ldg(&pv[lane + 32 * j]);
        s += a.x*a.x + a.y*a.y + a.z*a.z + a.w*a.w;
    }
    #pragma unroll
    for (int o = 16; o > 0; o >>= 1) s += __shfl_down_sync(0xffffffffu, s, o);
    if (lane == 0) g_psq[row] = s;
}

// ---- main: one block = one class-tile of G boxes ----
__global__ __launch_bounds__(256) void proto_match_kernel(
    const float* __restrict__ feats,
    const int*   __restrict__ plabels,
    float* __restrict__ out,
    int N)
{
    const int c    = blockIdx.y;
    const int tile = blockIdx.x;
    const int cnt  = g_hist[c];
    const int cnt_tile = min(G, cnt - tile * G);
    if (cnt_tile <= 0) return;
    const int start0 = g_off[c] + tile * G;

    const int tid  = threadIdx.x;
    const int lane = tid & 31;
    const int wid  = tid >> 5;
    const int p    = tid & 63;        // proto owned by this thread
    const int bq   = tid >> 6;        // box-pair group (0..3)

    __shared__ float f[G][DDIM];      // 16 KB
    __shared__ float dot_sh[G][PCNT];
    __shared__ float l1_sh[G][PCNT];
    __shared__ float fsq_sh[G];

    // ---- stage G feature vectors (warp w -> box w), compute ||f||^2 ----
    {
        int nb = g_sorted[start0 + min(wid, cnt_tile - 1)];
        const float4* src = reinterpret_cast<const float4*>(feats + (size_t)nb * DDIM);
        float4* dst = reinterpret_cast<float4*>(&f[wid][0]);
        float sq = 0.f;
        #pragma unroll
        for (int j = 0; j < 4; j++) {
            float4 v = __ldg(&src[lane + 32 * j]);
            dst[lane + 32 * j] = v;
            sq += v.x*v.x + v.y*v.y + v.z*v.z + v.w*v.w;
        }
        #pragma unroll
        for (int o = 16; o > 0; o >>= 1) sq += __shfl_down_sync(0xffffffffu, sq, o);
        if (lane == 0) fsq_sh[wid] = sq;
    }
    __syncthreads();

    // ---- main loop: thread owns (proto p) x (boxes 2bq, 2bq+1), full D ----
    const int b0 = 2 * bq, b1 = 2 * bq + 1;
    const float2* pt = reinterpret_cast<const float2*>(g_pT)
                       + (size_t)c * (256 * PCNT) + p;
    const float* fb0 = &f[b0][0];
    const float* fb1 = &f[b1][0];

    float dot0 = 0.f, dot1 = 0.f, l10 = 0.f, l11 = 0.f;
    #pragma unroll 4
    for (int d2 = 0; d2 < 256; d2 += 2) {
        float2 q0 = __ldg(&pt[(size_t)d2 * PCNT]);          // dims 2d2, 2d2+1
        float2 q1 = __ldg(&pt[(size_t)(d2 + 1) * PCNT]);    // dims 2d2+2, 2d2+3
        float4 fa = *reinterpret_cast<const float4*>(fb0 + 2 * d2);
        float4 fc = *reinterpret_cast<const float4*>(fb1 + 2 * d2);
        dot0 += q0.x*fa.x + q0.y*fa.y + q1.x*fa.z + q1.y*fa.w;
        l10  += fabsf(fa.x - q0.x) + fabsf(fa.y - q0.y)
              + fabsf(fa.z - q1.x) + fabsf(fa.w - q1.y);
        dot1 += q0.x*fc.x + q0.y*fc.y + q1.x*fc.z + q1.y*fc.w;
        l11  += fabsf(fc.x - q0.x) + fabsf(fc.y - q0.y)
              + fabsf(fc.z - q1.x) + fabsf(fc.w - q1.y);
    }
    dot_sh[b0][p] = dot0;  dot_sh[b1][p] = dot1;
    l1_sh[b0][p]  = l10;   l1_sh[b1][p]  = l11;
    __syncthreads();

    // ---- epilogue: warp w handles box w ----
    {
        const int b = wid;
        const bool valid = (b < cnt_tile);
        const int n = g_sorted[start0 + (valid ? b : 0)];
        const float fsq   = fsq_sh[b];
        const float fnorm = fmaxf(sqrtf(fsq), 1e-8f);

        float dt0 = dot_sh[b][lane], dt1 = dot_sh[b][lane + 32];
        float la0 = l1_sh[b][lane],  la1 = l1_sh[b][lane + 32];
        float ps0 = g_psq[c * PCNT + lane], ps1 = g_psq[c * PCNT + lane + 32];
        float pn0 = fmaxf(sqrtf(ps0), 1e-8f), pn1 = fmaxf(sqrtf(ps1), 1e-8f);

        float dd0[3], dd1[3];
        dd0[0] = 1.f - dt0 / (fnorm * pn0);
        dd1[0] = 1.f - dt1 / (fnorm * pn1);
        dd0[1] = la0 * (1.f / DDIM);
        dd1[1] = la1 * (1.f / DDIM);
        dd0[2] = (fsq - 2.f * dt0 + ps0) * (1.f / DDIM);
        dd1[2] = (fsq - 2.f * dt1 + ps1) * (1.f / DDIM);

        float avg0 = 0.f, avg1 = 0.f;
        #pragma unroll
        for (int m = 0; m < 3; m++) {
            float s0 = 1.f / (dd0[m] + 1e-5f);
            float s1 = 1.f / (dd1[m] + 1e-5f);
            float mx = fmaxf(s0, s1);
            #pragma unroll
            for (int o = 16; o > 0; o >>= 1) mx = fmaxf(mx, __shfl_xor_sync(0xffffffffu, mx, o));
            float e0 = expf(s0 - mx), e1 = expf(s1 - mx);
            float sum = e0 + e1;
            #pragma unroll
            for (int o = 16; o > 0; o >>= 1) sum += __shfl_xor_sync(0xffffffffu, sum, o);
            float inv = 1.f / sum;
            avg0 += e0 * inv;
            avg1 += e1 * inv;
        }
        avg0 *= (1.f / 3.f);
        avg1 *= (1.f / 3.f);

        if (valid) {
            out[(size_t)N + (size_t)n * PCNT + lane]      = avg0;
            out[(size_t)N + (size_t)n * PCNT + lane + 32] = avg1;
        }

        // argmax, first occurrence on ties
        float a0 = avg0; int i0 = lane;
        if (avg1 > a0) { a0 = avg1; i0 = lane + 32; }
        #pragma unroll
        for (int o = 16; o > 0; o >>= 1) {
            float ao = __shfl_xor_sync(0xffffffffu, a0, o);
            int   io = __shfl_xor_sync(0xffffffffu, i0, o);
            if (ao > a0 || (ao == a0 && io < i0)) { a0 = ao; i0 = io; }
        }
        if (lane == 0 && valid) out[n] = (float)plabels[c * PCNT + i0];
    }
}

extern "C" void kernel_launch(void* const* d_in, const int* in_sizes, int n_in,
                              void* d_out, int out_size) {
    const float* feats   = (const float*)d_in[0];   // [N, 512]
    const float* protos  = (const float*)d_in[1];   // [100, 64, 512]
    const int*   cls_ids = (const int*)d_in[2];     // [N]
    const int*   plabels = (const int*)d_in[3];     // [100, 64]
    float* out = (float*)d_out;

    int N = in_sizes[0] / DDIM;   // 4096

    zero_kernel<<<1, 256>>>();
    hist_kernel<<<(NBOX + 255) / 256, 256>>>(cls_ids);
    scan_kernel<<<1, 128>>>();
    scatter_kernel<<<(NBOX + 255) / 256, 256>>>(cls_ids);
    {
        dim3 g(DDIM / 32, PCNT / 32, CCNT);
        transpose_kernel<<<g, 256>>>(protos);
    }
    psq_kernel<<<(CCNT * PCNT + 7) / 8, 256>>>(protos);
    {
        dim3 g(TILES, CCNT);
        proto_match_kernel<<<g, 256>>>(feats, plabels, out, N);
    }
}